// round 1
// baseline (speedup 1.0000x reference)
#include <cuda_runtime.h>
#include <cuda_bf16.h>

// Problem constants: q [2,1024,128], k [2,1024,128], queue [128,65536]
#define NV 2
#define NN 1024
#define DD 128
#define KK 65536
#define BT 128   // tile size (rows and cols)

// ---------------- scratch (no allocations allowed) ----------------
__device__ float g_nq[NV * NN];          // row squared norms of q
__device__ float g_EQ[NN], g_TQ[NN];     // queue-part sums (shared across views)
__device__ float g_EI[NV * NN], g_TI[NV * NN]; // intra-part sums per view
__device__ float g_loss1;

// ---------------- kernels ----------------
__global__ void zero_kernel() {
    int t = blockIdx.x * blockDim.x + threadIdx.x;
    if (t < NN) { g_EQ[t] = 0.f; g_TQ[t] = 0.f; }
    if (t < NV * NN) { g_EI[t] = 0.f; g_TI[t] = 0.f; }
    if (t == 0) g_loss1 = 0.f;
}

// warp-per-task: tasks 0..2047 = row norms of q; 2048..4095 = loss1 rows
__global__ void prep_kernel(const float* __restrict__ q, const float* __restrict__ k) {
    int w = (blockIdx.x * blockDim.x + threadIdx.x) >> 5;
    int lane = threadIdx.x & 31;
    if (w < NV * NN) {
        const float* row = q + (size_t)w * DD;
        float s = 0.f;
        #pragma unroll
        for (int t = 0; t < DD / 32; t++) { float v = row[lane + t * 32]; s = fmaf(v, v, s); }
        #pragma unroll
        for (int m = 16; m >= 1; m >>= 1) s += __shfl_xor_sync(0xffffffffu, s, m);
        if (lane == 0) g_nq[w] = s;
    } else {
        int t2 = w - NV * NN;           // 0..2047
        int x = t2 >> 10, i = t2 & (NN - 1);
        const float* qr = q + ((size_t)x * NN + i) * DD;
        const float* kr = k + ((size_t)(1 - x) * NN + i) * DD;
        float s = 0.f;
        #pragma unroll
        for (int t = 0; t < DD / 32; t++) {
            float d = qr[lane + t * 32] - kr[lane + t * 32];
            s = fmaf(d, d, s);
        }
        #pragma unroll
        for (int m = 16; m >= 1; m >>= 1) s += __shfl_xor_sync(0xffffffffu, s, m);
        if (lane == 0) atomicAdd(&g_loss1, s);
    }
}

// mode 0: rows = q[0] tile (blockIdx.y), cols = queue tile (blockIdx.x); s = 2 - 2*dot
// mode 1: rows/cols = q[x] tiles (x = blockIdx.z); s = nq_i + nq_j - 2*dot, skip diagonal
__global__ __launch_bounds__(256) void gemm_fused(const float* __restrict__ q,
                                                  const float* __restrict__ queue,
                                                  int mode) {
    extern __shared__ float sm[];
    float* As = sm;             // [DD][BT] transposed: As[d*BT + i]
    float* Bs = sm + DD * BT;   // [DD][BT]
    int tid = threadIdx.x;
    int i0 = blockIdx.y * BT;
    int j0 = blockIdx.x * BT;
    int x = (mode == 0) ? 0 : blockIdx.z;
    const float* Abase = q + (size_t)x * NN * DD;

    // load A tile transposed: As[d][i] = A[(i0+i)*DD + d]
    for (int t = tid; t < BT * DD / 4; t += 256) {
        int i = t & (BT - 1), d4 = t >> 7;
        float4 v = *(const float4*)(Abase + (size_t)(i0 + i) * DD + d4 * 4);
        As[(d4 * 4 + 0) * BT + i] = v.x;
        As[(d4 * 4 + 1) * BT + i] = v.y;
        As[(d4 * 4 + 2) * BT + i] = v.z;
        As[(d4 * 4 + 3) * BT + i] = v.w;
    }
    if (mode == 0) {
        // queue is [DD, KK] row-major: Bs[d][j] = queue[d*KK + j0 + j]  (coalesced)
        for (int t = tid; t < BT * DD / 4; t += 256) {
            int j4 = t & 31, d = t >> 5;
            float4 v = *(const float4*)(queue + (size_t)d * KK + j0 + j4 * 4);
            *(float4*)(Bs + d * BT + j4 * 4) = v;
        }
    } else {
        // Bs[d][j] = q[x][(j0+j)*DD + d]  (transpose load)
        for (int t = tid; t < BT * DD / 4; t += 256) {
            int j = t & (BT - 1), d4 = t >> 7;
            float4 v = *(const float4*)(Abase + (size_t)(j0 + j) * DD + d4 * 4);
            Bs[(d4 * 4 + 0) * BT + j] = v.x;
            Bs[(d4 * 4 + 1) * BT + j] = v.y;
            Bs[(d4 * 4 + 2) * BT + j] = v.z;
            Bs[(d4 * 4 + 3) * BT + j] = v.w;
        }
    }
    __syncthreads();

    int r = tid >> 4;   // 0..15 -> rows r*8..r*8+7
    int c = tid & 15;   // 0..15 -> cols c*8..c*8+7
    float acc[8][8];
    #pragma unroll
    for (int ii = 0; ii < 8; ii++)
        #pragma unroll
        for (int jj = 0; jj < 8; jj++) acc[ii][jj] = 0.f;

    #pragma unroll 4
    for (int kk = 0; kk < DD; kk++) {
        float4 a0 = *(const float4*)(As + kk * BT + r * 8);
        float4 a1 = *(const float4*)(As + kk * BT + r * 8 + 4);
        float4 b0 = *(const float4*)(Bs + kk * BT + c * 8);
        float4 b1 = *(const float4*)(Bs + kk * BT + c * 8 + 4);
        float a[8] = {a0.x, a0.y, a0.z, a0.w, a1.x, a1.y, a1.z, a1.w};
        float b[8] = {b0.x, b0.y, b0.z, b0.w, b1.x, b1.y, b1.z, b1.w};
        #pragma unroll
        for (int ii = 0; ii < 8; ii++)
            #pragma unroll
            for (int jj = 0; jj < 8; jj++)
                acc[ii][jj] = fmaf(a[ii], b[jj], acc[ii][jj]);
    }

    float eS[8], tS[8];
    if (mode == 0) {
        #pragma unroll
        for (int ii = 0; ii < 8; ii++) {
            float e = 0.f, tv = 0.f;
            #pragma unroll
            for (int jj = 0; jj < 8; jj++) {
                float s = 2.f - 2.f * acc[ii][jj];
                float w = __expf(-s);
                e += w;
                tv = fmaf(s, w, tv);
            }
            eS[ii] = e; tS[ii] = tv;
        }
    } else {
        float nr[8], ncl[8];
        #pragma unroll
        for (int ii = 0; ii < 8; ii++) nr[ii] = g_nq[x * NN + i0 + r * 8 + ii];
        #pragma unroll
        for (int jj = 0; jj < 8; jj++) ncl[jj] = g_nq[x * NN + j0 + c * 8 + jj];
        #pragma unroll
        for (int ii = 0; ii < 8; ii++) {
            float e = 0.f, tv = 0.f;
            int gi = i0 + r * 8 + ii;
            #pragma unroll
            for (int jj = 0; jj < 8; jj++) {
                int gj = j0 + c * 8 + jj;
                if (gi != gj) {
                    float s = nr[ii] + ncl[jj] - 2.f * acc[ii][jj];
                    float w = __expf(-s);
                    e += w;
                    tv = fmaf(s, w, tv);
                }
            }
            eS[ii] = e; tS[ii] = tv;
        }
    }

    // reduce over the 16 c-lanes (lanes 0-15 / 16-31 of each warp share r)
    #pragma unroll
    for (int m = 1; m < 16; m <<= 1) {
        #pragma unroll
        for (int ii = 0; ii < 8; ii++) {
            eS[ii] += __shfl_xor_sync(0xffffffffu, eS[ii], m);
            tS[ii] += __shfl_xor_sync(0xffffffffu, tS[ii], m);
        }
    }
    if (c == 0) {
        float* E = (mode == 0) ? g_EQ : (g_EI + x * NN);
        float* T = (mode == 0) ? g_TQ : (g_TI + x * NN);
        #pragma unroll
        for (int ii = 0; ii < 8; ii++) {
            atomicAdd(&E[i0 + r * 8 + ii], eS[ii]);
            atomicAdd(&T[i0 + r * 8 + ii], tS[ii]);
        }
    }
}

__global__ void finalize_kernel(float* __restrict__ out) {
    int i = threadIdx.x;   // 1024 threads
    float v = 0.f;
    #pragma unroll
    for (int x = 0; x < NV; x++) {
        float E = g_EQ[i] + g_EI[x * NN + i];
        float T = g_TQ[i] + g_TI[x * NN + i];
        v -= T / E;
    }
    __shared__ float red[32];
    #pragma unroll
    for (int m = 16; m >= 1; m >>= 1) v += __shfl_xor_sync(0xffffffffu, v, m);
    if ((i & 31) == 0) red[i >> 5] = v;
    __syncthreads();
    if (i < 32) {
        float w = red[i];
        #pragma unroll
        for (int m = 16; m >= 1; m >>= 1) w += __shfl_xor_sync(0xffffffffu, w, m);
        if (i == 0) {
            out[0] = g_loss1 * (1.0f / (NV * NN));  // loss1 / v
            out[1] = w * (1.0f / (NV * NN));        // loss2 / v
        }
    }
}

// ---------------- launcher ----------------
extern "C" void kernel_launch(void* const* d_in, const int* in_sizes, int n_in,
                              void* d_out, int out_size) {
    const float* q     = (const float*)d_in[0];
    const float* k     = (const float*)d_in[1];
    const float* queue = (const float*)d_in[2];
    float* out = (float*)d_out;

    const int smem = 2 * BT * DD * sizeof(float);  // 128 KB
    cudaFuncSetAttribute(gemm_fused, cudaFuncAttributeMaxDynamicSharedMemorySize, smem);

    zero_kernel<<<8, 256>>>();
    prep_kernel<<<(2 * NV * NN * 32) / 256, 256>>>(q, k);
    gemm_fused<<<dim3(KK / BT, NN / BT, 1), 256, smem>>>(q, queue, 0);   // queue part
    gemm_fused<<<dim3(NN / BT, NN / BT, NV), 256, smem>>>(q, queue, 1);  // intra part
    finalize_kernel<<<1, 1024>>>(out);
}

// round 2
// speedup vs baseline: 3.5612x; 3.5612x over previous
#include <cuda_runtime.h>
#include <cuda_bf16.h>
#include <cstdint>

// Problem constants: q [2,1024,128], k [2,1024,128], queue [128,65536]
#define NV 2
#define NN 1024
#define DD 128
#define KK 65536
#define BT 128           // CTA tile (rows and cols)
#define KC 64            // k-chunk
#define SA 68            // A smem stride (floats)  -> bank = lane (conflict free)
#define SB0 136          // mode0 B smem stride     -> bank = 8*tg+g (conflict free)
#define SB1 68           // mode1 B smem stride     -> bank = 4*g+tg (conflict free)
#define A_FLOATS (BT * SA)      // 8704
#define B_FLOATS 8704           // max(64*136, 128*68) = 8704
#define STAGE_FLOATS (A_FLOATS + B_FLOATS)   // 17408
#define SMEM_BYTES (2 * STAGE_FLOATS * 4)    // 139264

// ---------------- scratch (no allocations allowed) ----------------
__device__ float g_nq[NV * NN];
__device__ float g_EQ[NN], g_TQ[NN];
__device__ float g_EI[NV * NN], g_TI[NV * NN];
__device__ float g_loss1;

// ---------------- helpers ----------------
__device__ __forceinline__ uint32_t f2tf32(float f) {
    uint32_t r;
    asm("cvt.rna.tf32.f32 %0, %1;" : "=r"(r) : "f"(f));
    return r;
}
__device__ __forceinline__ void cp16(float* dst, const float* src) {
    uint32_t d = (uint32_t)__cvta_generic_to_shared(dst);
    asm volatile("cp.async.cg.shared.global [%0], [%1], 16;" :: "r"(d), "l"(src));
}
__device__ __forceinline__ void mma_tf32(float* c, const uint32_t* a, const uint32_t* b) {
    asm volatile(
        "mma.sync.aligned.m16n8k8.row.col.f32.tf32.tf32.f32 "
        "{%0,%1,%2,%3}, {%4,%5,%6,%7}, {%8,%9}, {%0,%1,%2,%3};"
        : "+f"(c[0]), "+f"(c[1]), "+f"(c[2]), "+f"(c[3])
        : "r"(a[0]), "r"(a[1]), "r"(a[2]), "r"(a[3]), "r"(b[0]), "r"(b[1]));
}

// ---------------- small kernels ----------------
__global__ void zero_kernel() {
    int t = blockIdx.x * blockDim.x + threadIdx.x;
    if (t < NN) { g_EQ[t] = 0.f; g_TQ[t] = 0.f; }
    if (t < NV * NN) { g_EI[t] = 0.f; g_TI[t] = 0.f; }
    if (t == 0) g_loss1 = 0.f;
}

__global__ void prep_kernel(const float* __restrict__ q, const float* __restrict__ k) {
    int w = (blockIdx.x * blockDim.x + threadIdx.x) >> 5;
    int lane = threadIdx.x & 31;
    if (w < NV * NN) {
        const float* row = q + (size_t)w * DD;
        float s = 0.f;
        #pragma unroll
        for (int t = 0; t < DD / 32; t++) { float v = row[lane + t * 32]; s = fmaf(v, v, s); }
        #pragma unroll
        for (int m = 16; m >= 1; m >>= 1) s += __shfl_xor_sync(0xffffffffu, s, m);
        if (lane == 0) g_nq[w] = s;
    } else {
        int t2 = w - NV * NN;
        int x = t2 >> 10, i = t2 & (NN - 1);
        const float* qr = q + ((size_t)x * NN + i) * DD;
        const float* kr = k + ((size_t)(1 - x) * NN + i) * DD;
        float s = 0.f;
        #pragma unroll
        for (int t = 0; t < DD / 32; t++) {
            float d = qr[lane + t * 32] - kr[lane + t * 32];
            s = fmaf(d, d, s);
        }
        #pragma unroll
        for (int m = 16; m >= 1; m >>= 1) s += __shfl_xor_sync(0xffffffffu, s, m);
        if (lane == 0) atomicAdd(&g_loss1, s);
    }
}

// ---------------- tensor-core fused GEMM + softmax-stat epilogue ----------------
// MODE 0: A = q[0] rows (i), B = queue cols (j); s = 2 - 2*dot
// MODE 1: A = q[x] rows, B = q[x] rows; s = nq_i + nq_j - 2*dot, diagonal skipped
template <int MODE>
__global__ __launch_bounds__(256) void gemm_tc(const float* __restrict__ q,
                                               const float* __restrict__ queue) {
    extern __shared__ float sm[];
    const int tid = threadIdx.x;
    const int lane = tid & 31, wid = tid >> 5;
    const int wm = wid >> 1, wn = wid & 1;     // 4 x 2 warp grid, warp tile 32x64
    const int g = lane >> 2, tg = lane & 3;
    const int i0 = blockIdx.y * BT;
    const int j0 = blockIdx.x * BT;
    const int x = (MODE == 0) ? 0 : blockIdx.z;
    const float* Abase = q + (size_t)x * NN * DD;

    // ---- async copy both k-chunks (chunk = 64 of D=128) ----
    #pragma unroll
    for (int kc = 0; kc < 2; kc++) {
        float* As = sm + kc * STAGE_FLOATS;
        float* Bs = As + A_FLOATS;
        for (int t = tid; t < 2048; t += 256) {           // A: 128 rows x 16 float4
            int i = t >> 4, f = t & 15;
            cp16(As + i * SA + f * 4, Abase + (size_t)(i0 + i) * DD + kc * KC + f * 4);
        }
        if (MODE == 0) {
            for (int t = tid; t < 2048; t += 256) {       // B: 64 d-rows x 32 float4
                int d = t >> 5, f = t & 31;
                cp16(Bs + d * SB0 + f * 4, queue + (size_t)(kc * KC + d) * KK + j0 + f * 4);
            }
        } else {
            for (int t = tid; t < 2048; t += 256) {       // B: 128 n-rows x 16 float4
                int n = t >> 4, f = t & 15;
                cp16(Bs + n * SB1 + f * 4, Abase + (size_t)(j0 + n) * DD + kc * KC + f * 4);
            }
        }
        asm volatile("cp.async.commit_group;");
    }

    float acc[2][8][4];
    #pragma unroll
    for (int mt = 0; mt < 2; mt++)
        #pragma unroll
        for (int nt = 0; nt < 8; nt++)
            #pragma unroll
            for (int ci = 0; ci < 4; ci++) acc[mt][nt][ci] = 0.f;

    #pragma unroll
    for (int kc = 0; kc < 2; kc++) {
        if (kc == 0) asm volatile("cp.async.wait_group 1;");
        else         asm volatile("cp.async.wait_group 0;");
        __syncthreads();
        const float* As = sm + kc * STAGE_FLOATS;
        const float* Bs = As + A_FLOATS;

        #pragma unroll
        for (int ks = 0; ks < KC / 8; ks++) {
            const int kb = ks * 8;
            uint32_t a[2][4];
            #pragma unroll
            for (int mt = 0; mt < 2; mt++) {
                int r0 = wm * 32 + mt * 16 + g;
                a[mt][0] = f2tf32(As[r0 * SA + kb + tg]);
                a[mt][1] = f2tf32(As[(r0 + 8) * SA + kb + tg]);
                a[mt][2] = f2tf32(As[r0 * SA + kb + tg + 4]);
                a[mt][3] = f2tf32(As[(r0 + 8) * SA + kb + tg + 4]);
            }
            uint32_t b[8][2];
            #pragma unroll
            for (int nt = 0; nt < 8; nt++) {
                int cc = wn * 64 + nt * 8 + g;
                if (MODE == 0) {
                    b[nt][0] = f2tf32(Bs[(kb + tg) * SB0 + cc]);
                    b[nt][1] = f2tf32(Bs[(kb + tg + 4) * SB0 + cc]);
                } else {
                    b[nt][0] = f2tf32(Bs[cc * SB1 + kb + tg]);
                    b[nt][1] = f2tf32(Bs[cc * SB1 + kb + tg + 4]);
                }
            }
            #pragma unroll
            for (int mt = 0; mt < 2; mt++)
                #pragma unroll
                for (int nt = 0; nt < 8; nt++)
                    mma_tf32(acc[mt][nt], a[mt], b[nt]);
        }
    }

    // ---- fused epilogue: s -> exp(-s), per-row (E,T) partials ----
    float e[4] = {0.f, 0.f, 0.f, 0.f}, tS[4] = {0.f, 0.f, 0.f, 0.f};
    float nqi[4];
    if (MODE == 1) {
        #pragma unroll
        for (int mt = 0; mt < 2; mt++)
            #pragma unroll
            for (int h = 0; h < 2; h++)
                nqi[mt * 2 + h] = g_nq[x * NN + i0 + wm * 32 + mt * 16 + g + 8 * h];
    }
    #pragma unroll
    for (int mt = 0; mt < 2; mt++) {
        #pragma unroll
        for (int nt = 0; nt < 8; nt++) {
            #pragma unroll
            for (int ci = 0; ci < 4; ci++) {
                int h = ci >> 1;
                int gj = j0 + wn * 64 + nt * 8 + 2 * tg + (ci & 1);
                float dotv = acc[mt][nt][ci];
                float s;
                if (MODE == 0) {
                    s = 2.f - 2.f * dotv;
                } else {
                    int gi = i0 + wm * 32 + mt * 16 + g + 8 * h;
                    if (gi == gj) continue;
                    s = nqi[mt * 2 + h] + g_nq[x * NN + gj] - 2.f * dotv;
                }
                float w = __expf(-s);
                e[mt * 2 + h] += w;
                tS[mt * 2 + h] = fmaf(s, w, tS[mt * 2 + h]);
            }
        }
    }
    // reduce across the 4 lanes (tg) that share each row
    #pragma unroll
    for (int m = 1; m < 4; m <<= 1) {
        #pragma unroll
        for (int ri = 0; ri < 4; ri++) {
            e[ri]  += __shfl_xor_sync(0xffffffffu, e[ri], m);
            tS[ri] += __shfl_xor_sync(0xffffffffu, tS[ri], m);
        }
    }
    if (tg == 0) {
        float* E = (MODE == 0) ? g_EQ : (g_EI + x * NN);
        float* T = (MODE == 0) ? g_TQ : (g_TI + x * NN);
        #pragma unroll
        for (int mt = 0; mt < 2; mt++)
            #pragma unroll
            for (int h = 0; h < 2; h++) {
                int gi = i0 + wm * 32 + mt * 16 + g + 8 * h;
                atomicAdd(&E[gi], e[mt * 2 + h]);
                atomicAdd(&T[gi], tS[mt * 2 + h]);
            }
    }
}

__global__ void finalize_kernel(float* __restrict__ out) {
    int i = threadIdx.x;   // 1024 threads
    float v = 0.f;
    #pragma unroll
    for (int x = 0; x < NV; x++) {
        float E = g_EQ[i] + g_EI[x * NN + i];
        float T = g_TQ[i] + g_TI[x * NN + i];
        v -= T / E;
    }
    __shared__ float red[32];
    #pragma unroll
    for (int m = 16; m >= 1; m >>= 1) v += __shfl_xor_sync(0xffffffffu, v, m);
    if ((i & 31) == 0) red[i >> 5] = v;
    __syncthreads();
    if (i < 32) {
        float w = red[i];
        #pragma unroll
        for (int m = 16; m >= 1; m >>= 1) w += __shfl_xor_sync(0xffffffffu, w, m);
        if (i == 0) {
            out[0] = g_loss1 * (1.0f / (NV * NN));
            out[1] = w * (1.0f / (NV * NN));
        }
    }
}

// ---------------- launcher ----------------
extern "C" void kernel_launch(void* const* d_in, const int* in_sizes, int n_in,
                              void* d_out, int out_size) {
    const float* q     = (const float*)d_in[0];
    const float* k     = (const float*)d_in[1];
    const float* queue = (const float*)d_in[2];
    float* out = (float*)d_out;

    cudaFuncSetAttribute(gemm_tc<0>, cudaFuncAttributeMaxDynamicSharedMemorySize, SMEM_BYTES);
    cudaFuncSetAttribute(gemm_tc<1>, cudaFuncAttributeMaxDynamicSharedMemorySize, SMEM_BYTES);

    zero_kernel<<<8, 256>>>();
    prep_kernel<<<(2 * NV * NN * 32) / 256, 256>>>(q, k);
    gemm_tc<0><<<dim3(KK / BT, NN / BT, 1), 256, SMEM_BYTES>>>(q, queue);   // queue part
    gemm_tc<1><<<dim3(NN / BT, NN / BT, NV), 256, SMEM_BYTES>>>(q, queue);  // intra part
    finalize_kernel<<<1, 1024>>>(out);
}

// round 4
// speedup vs baseline: 7.2500x; 2.0358x over previous
#include <cuda_runtime.h>
#include <cuda_bf16.h>
#include <cstdint>

// Problem: q [2,1024,128] (rows unit-norm), k [2,1024,128], queue [128,65536] (cols unit-norm)
#define NV 2
#define NN 1024
#define DD 128
#define KK 65536
#define QT 512              // queue tiles of 128 cols
#define TILE_U32 8192       // 32KB bf16 tile image (128 rows x 128 k, swizzled)

// ---------------- scratch (static device globals; no allocation) ----------------
__device__ __align__(128) uint32_t g_qu[QT * TILE_U32];       // queue tile images (16.8MB)
__device__ __align__(128) uint32_t g_qt[NV * 8 * TILE_U32];   // q tile images (512KB)
__device__ float g_EQ[NN], g_WQ[NN];          // queue part: sum e^{-s}, sum d*e^{-s}
__device__ float g_EI[NV * NN], g_WI[NV * NN];
__device__ float g_loss1;

// ---------------- helpers ----------------
__device__ __forceinline__ uint32_t smem_u32(const void* p) {
    uint32_t a;
    asm("{ .reg .u64 t; cvta.to.shared.u64 t, %1; cvt.u32.u64 %0, t; }" : "=r"(a) : "l"(p));
    return a;
}
__device__ __forceinline__ void cp16(uint32_t daddr, const void* src) {
    asm volatile("cp.async.cg.shared.global [%0], [%1], 16;" :: "r"(daddr), "l"(src));
}
__device__ __forceinline__ void ldsm_x4(uint32_t* r, uint32_t addr) {
    asm volatile("ldmatrix.sync.aligned.m8n8.x4.shared.b16 {%0,%1,%2,%3}, [%4];"
                 : "=r"(r[0]), "=r"(r[1]), "=r"(r[2]), "=r"(r[3]) : "r"(addr));
}
__device__ __forceinline__ void mma_bf16(float* c, const uint32_t* a, const uint32_t* b) {
    asm volatile(
        "mma.sync.aligned.m16n8k16.row.col.f32.bf16.bf16.f32 "
        "{%0,%1,%2,%3}, {%4,%5,%6,%7}, {%8,%9}, {%0,%1,%2,%3};"
        : "+f"(c[0]), "+f"(c[1]), "+f"(c[2]), "+f"(c[3])
        : "r"(a[0]), "r"(a[1]), "r"(a[2]), "r"(a[3]), "r"(b[0]), "r"(b[1]));
}
// swizzled u32 index inside a 128x128 bf16 tile: row stride 256B, 16B chunks XOR (row&7)
__device__ __forceinline__ uint32_t tidx(uint32_t row, uint32_t kp /*k/2*/) {
    return row * 64u + ((((kp >> 2) ^ (row & 7u))) << 2) + (kp & 3u);
}

// ---------------- small kernels ----------------
__global__ void zero_kernel() {
    int t = blockIdx.x * blockDim.x + threadIdx.x;
    if (t < NN) { g_EQ[t] = 0.f; g_WQ[t] = 0.f; }
    if (t < NV * NN) { g_EI[t] = 0.f; g_WI[t] = 0.f; }
    if (t == 0) g_loss1 = 0.f;
}

// q -> bf16 swizzled tile images. 16 tiles (tile = v*8+rb).
__global__ void conv_q(const float* __restrict__ q) {
    int t = blockIdx.x;
    const float* src = q + (size_t)t * 128 * DD;
    uint32_t* dst = g_qt + (size_t)t * TILE_U32;
    #pragma unroll 4
    for (int it = 0; it < 32; it++) {
        int idx = it * 256 + threadIdx.x;
        int row = idx >> 6, kp = idx & 63;
        float2 v = *(const float2*)(src + row * DD + 2 * kp);
        __nv_bfloat162 b = __floats2bfloat162_rn(v.x, v.y);
        dst[tidx(row, kp)] = *(uint32_t*)&b;
    }
}

// queue [D,K] -> per-tile transposed ([n][k]) bf16 swizzled images. 512 tiles.
__global__ void conv_qu(const float* __restrict__ queue) {
    extern __shared__ float sf[];     // 128 x 129
    int t = blockIdx.x;
    for (int it = 0; it < 64; it++) {
        int idx = it * 256 + threadIdx.x;
        int d = idx >> 7, j = idx & 127;
        sf[d * 129 + j] = queue[(size_t)d * KK + t * 128 + j];
    }
    __syncthreads();
    uint32_t* dst = g_qu + (size_t)t * TILE_U32;
    #pragma unroll 4
    for (int it = 0; it < 32; it++) {
        int idx = it * 256 + threadIdx.x;
        int n = idx >> 6, kp = idx & 63;
        __nv_bfloat162 b = __floats2bfloat162_rn(sf[(2 * kp) * 129 + n], sf[(2 * kp + 1) * 129 + n]);
        dst[tidx(n, kp)] = *(uint32_t*)&b;
    }
}

// loss1: sum over x,i of ||q[x,i]-k[1-x,i]||^2  (warp per row)
__global__ void prep_kernel(const float* __restrict__ q, const float* __restrict__ k) {
    int w = (blockIdx.x * blockDim.x + threadIdx.x) >> 5;   // 0..2047
    int lane = threadIdx.x & 31;
    int x = w >> 10, i = w & (NN - 1);
    const float* qr = q + ((size_t)x * NN + i) * DD;
    const float* kr = k + ((size_t)(1 - x) * NN + i) * DD;
    float s = 0.f;
    #pragma unroll
    for (int t = 0; t < DD / 32; t++) {
        float d = qr[lane + t * 32] - kr[lane + t * 32];
        s = fmaf(d, d, s);
    }
    #pragma unroll
    for (int m = 16; m >= 1; m >>= 1) s += __shfl_xor_sync(0xffffffffu, s, m);
    if (lane == 0) atomicAdd(&g_loss1, s);
}

// ---------------- persistent bf16 mma.sync GEMM + fused epilogue ----------------
// bid < 512: queue part: rows = q[0] block rb (bid>>6), B tiles = j-group (bid&63) * 8
// bid >= 512: intra part: view x, row block rb; B tiles = all 8 tiles of q[x]
__global__ __launch_bounds__(256, 2) void gemm_ws() {
    extern __shared__ __align__(128) char sm[];
    const uint32_t sb = smem_u32(sm);
    const uint32_t o_A = sb, o_B0 = sb + 32768, o_B1 = sb + 65536;
    const int tid = threadIdx.x, lane = tid & 31, wid = tid >> 5;
    const int wm = wid >> 1, wn = wid & 1;        // 4x2 warps, warp tile 32x64
    const int bid = blockIdx.x;

    const uint32_t *Asrc, *Bsrc;
    float *Eout, *Wout;
    int rowbase;
    if (bid < 512) {
        int rb = bid >> 6, jg = bid & 63;
        Asrc = g_qt + (size_t)rb * TILE_U32;                  // view 0 rows
        Bsrc = g_qu + (size_t)(jg * 8) * TILE_U32;
        Eout = g_EQ; Wout = g_WQ; rowbase = rb * 128;
    } else {
        int id = bid - 512, x = id >> 3, rb = id & 7;
        Asrc = g_qt + (size_t)(x * 8 + rb) * TILE_U32;
        Bsrc = g_qt + (size_t)(x * 8) * TILE_U32;
        Eout = g_EI + x * NN; Wout = g_WI + x * NN; rowbase = rb * 128;
    }

    // prologue: A + B0 (contiguous 32KB copies), one commit group
    #pragma unroll
    for (int c = 0; c < 8; c++) cp16(o_A + (c * 256 + tid) * 16, Asrc + (c * 256 + tid) * 4);
    #pragma unroll
    for (int c = 0; c < 8; c++) cp16(o_B0 + (c * 256 + tid) * 16, Bsrc + (c * 256 + tid) * 4);
    asm volatile("cp.async.commit_group;");

    // per-lane ldmatrix address components
    const uint32_t swzA = (uint32_t)(lane & 7);
    const uint32_t rbA0 = (uint32_t)(wm * 32 + (lane & 15)) * 256u;   // + mt*16*256
    const uint32_t hiA = (uint32_t)(lane >> 4);                       // k-chunk bit
    const uint32_t nrowb = (uint32_t)(wn * 64 + ((lane >> 4) & 1) * 8 + (lane & 7));
    const uint32_t kbB = (uint32_t)((lane >> 3) & 1);
    const uint32_t swzB = (uint32_t)(lane & 7);

    float acc[2][8][4];
    #pragma unroll
    for (int mt = 0; mt < 2; mt++)
        #pragma unroll
        for (int nt = 0; nt < 8; nt++)
            #pragma unroll
            for (int ci = 0; ci < 4; ci++) acc[mt][nt][ci] = 0.f;
    float E[4] = {0.f, 0.f, 0.f, 0.f}, W[4] = {0.f, 0.f, 0.f, 0.f};

    for (int t = 0; t < 8; t++) {
        const int buf = t & 1;
        if (t < 7) {          // prefetch next B into the other buffer
            uint32_t dstB = buf ? o_B0 : o_B1;
            const uint32_t* s = Bsrc + (size_t)(t + 1) * TILE_U32;
            #pragma unroll
            for (int c = 0; c < 8; c++) cp16(dstB + (c * 256 + tid) * 16, s + (c * 256 + tid) * 4);
            asm volatile("cp.async.commit_group;");
            asm volatile("cp.async.wait_group 1;");
        } else {
            asm volatile("cp.async.wait_group 0;");
        }
        __syncthreads();      // current B visible to all warps

        const uint32_t Bs = buf ? o_B1 : o_B0;
        #pragma unroll
        for (int ks = 0; ks < 8; ks++) {
            uint32_t a[2][4];
            #pragma unroll
            for (int mt = 0; mt < 2; mt++)
                ldsm_x4(a[mt], o_A + rbA0 + (uint32_t)(mt * 16 * 256)
                               + ((((uint32_t)(2 * ks) + hiA) ^ swzA) << 4));
            #pragma unroll
            for (int p = 0; p < 4; p++) {
                uint32_t bb[4];
                ldsm_x4(bb, Bs + (nrowb + (uint32_t)(p * 16)) * 256u
                            + ((((uint32_t)(2 * ks) + kbB) ^ swzB) << 4));
                mma_bf16(acc[0][2 * p],     a[0], bb);
                mma_bf16(acc[0][2 * p + 1], a[0], bb + 2);
                mma_bf16(acc[1][2 * p],     a[1], bb);
                mma_bf16(acc[1][2 * p + 1], a[1], bb + 2);
            }
        }

        // fused epilogue: w = e^{2d-2}; E += w; W += d*w; rezero acc
        #pragma unroll
        for (int mt = 0; mt < 2; mt++)
            #pragma unroll
            for (int nt = 0; nt < 8; nt++)
                #pragma unroll
                for (int ci = 0; ci < 4; ci++) {
                    float d = acc[mt][nt][ci];
                    acc[mt][nt][ci] = 0.f;
                    float e2 = fmaf(d, 2.885390082f, -2.885390082f);  // (2d-2)*log2(e)
                    float w;
                    asm("ex2.approx.f32 %0, %1;" : "=f"(w) : "f"(e2));
                    int idx = mt * 2 + (ci >> 1);
                    E[idx] += w;
                    W[idx] = fmaf(d, w, W[idx]);
                }
        __syncthreads();      // all warps done with B[t] before it is overwritten
    }

    // reduce over the 4 lanes sharing each row (lane&3), then atomics
    #pragma unroll
    for (int m = 1; m < 4; m <<= 1)
        #pragma unroll
        for (int ri = 0; ri < 4; ri++) {
            E[ri] += __shfl_xor_sync(0xffffffffu, E[ri], m);
            W[ri] += __shfl_xor_sync(0xffffffffu, W[ri], m);
        }
    if ((lane & 3) == 0) {
        int g = lane >> 2;
        #pragma unroll
        for (int mt = 0; mt < 2; mt++)
            #pragma unroll
            for (int h = 0; h < 2; h++) {
                int row = rowbase + wm * 32 + mt * 16 + 8 * h + g;
                atomicAdd(&Eout[row], E[mt * 2 + h]);
                atomicAdd(&Wout[row], W[mt * 2 + h]);
            }
    }
}

__global__ void finalize_kernel(float* __restrict__ out) {
    int i = threadIdx.x;   // 1024 threads
    float v = 0.f;
    #pragma unroll
    for (int x = 0; x < NV; x++) {
        float S  = g_EQ[i] + g_EI[x * NN + i];   // sum e^{-s} incl. diagonal (=1)
        float Wt = g_WQ[i] + g_WI[x * NN + i];   // sum d*e^{-s}
        float T = 2.f * (S - Wt);                // sum s*e^{-s} (diag adds 0)
        float E = S - 1.f;                       // drop diagonal
        v -= T / E;
    }
    __shared__ float red[32];
    #pragma unroll
    for (int m = 16; m >= 1; m >>= 1) v += __shfl_xor_sync(0xffffffffu, v, m);
    if ((i & 31) == 0) red[i >> 5] = v;
    __syncthreads();
    if (i < 32) {
        float w = red[i];
        #pragma unroll
        for (int m = 16; m >= 1; m >>= 1) w += __shfl_xor_sync(0xffffffffu, w, m);
        if (i == 0) {
            out[0] = g_loss1 * (1.0f / (NV * NN));
            out[1] = w * (1.0f / (NV * NN));
        }
    }
}

// ---------------- launcher ----------------
extern "C" void kernel_launch(void* const* d_in, const int* in_sizes, int n_in,
                              void* d_out, int out_size) {
    const float* q     = (const float*)d_in[0];
    const float* k     = (const float*)d_in[1];
    const float* queue = (const float*)d_in[2];
    float* out = (float*)d_out;

    const int smem_gemm = 3 * 32768;              // A + B double buffer = 96KB
    const int smem_conv = 128 * 129 * 4;          // 66048
    cudaFuncSetAttribute(gemm_ws, cudaFuncAttributeMaxDynamicSharedMemorySize, smem_gemm);
    cudaFuncSetAttribute(conv_qu, cudaFuncAttributeMaxDynamicSharedMemorySize, smem_conv);

    zero_kernel<<<8, 256>>>();
    conv_q<<<16, 256>>>(q);
    conv_qu<<<512, 256, smem_conv>>>(queue);
    prep_kernel<<<256, 256>>>(q, k);
    gemm_ws<<<512 + 16, 256, smem_gemm>>>();
    finalize_kernel<<<1, 1024>>>(out);
}

// round 5
// speedup vs baseline: 7.9420x; 1.0955x over previous
#include <cuda_runtime.h>
#include <cuda_bf16.h>
#include <cstdint>

// Problem: q [2,1024,128] (rows unit-norm), k [2,1024,128] (rows unit-norm), queue [128,65536]
#define NV 2
#define NN 1024
#define DD 128
#define KK 65536
#define QT 512              // queue tiles of 128 cols
#define TILE_U32 8192       // 32KB bf16 tile image (128 rows x 128 k, swizzled)

// ---------------- scratch (static device globals; no allocation) ----------------
__device__ __align__(128) uint32_t g_qu[QT * TILE_U32];       // queue tile images (16.8MB)
__device__ __align__(128) uint32_t g_qt[NV * 8 * TILE_U32];   // q tile images (512KB)
__device__ float g_EQ[NN], g_WQ[NN];          // queue part: sum e^{-s}, sum d*e^{-s}
__device__ float g_EI[NV * NN], g_WI[NV * NN];
__device__ float g_l1part[256];               // loss1 per-block partials (overwritten)

// ---------------- helpers ----------------
__device__ __forceinline__ uint32_t smem_u32(const void* p) {
    uint32_t a;
    asm("{ .reg .u64 t; cvta.to.shared.u64 t, %1; cvt.u32.u64 %0, t; }" : "=r"(a) : "l"(p));
    return a;
}
__device__ __forceinline__ void cp16(uint32_t daddr, const void* src) {
    asm volatile("cp.async.cg.shared.global [%0], [%1], 16;" :: "r"(daddr), "l"(src));
}
__device__ __forceinline__ void ldsm_x4(uint32_t* r, uint32_t addr) {
    asm volatile("ldmatrix.sync.aligned.m8n8.x4.shared.b16 {%0,%1,%2,%3}, [%4];"
                 : "=r"(r[0]), "=r"(r[1]), "=r"(r[2]), "=r"(r[3]) : "r"(addr));
}
__device__ __forceinline__ void mma_bf16(float* c, const uint32_t* a, const uint32_t* b) {
    asm volatile(
        "mma.sync.aligned.m16n8k16.row.col.f32.bf16.bf16.f32 "
        "{%0,%1,%2,%3}, {%4,%5,%6,%7}, {%8,%9}, {%0,%1,%2,%3};"
        : "+f"(c[0]), "+f"(c[1]), "+f"(c[2]), "+f"(c[3])
        : "r"(a[0]), "r"(a[1]), "r"(a[2]), "r"(a[3]), "r"(b[0]), "r"(b[1]));
}
// swizzled u32 index inside a 128x128 bf16 tile: row stride 256B, 16B chunks XOR (row&7)
__device__ __forceinline__ uint32_t tidx(uint32_t row, uint32_t kp /*k/2*/) {
    return row * 64u + ((((kp >> 2) ^ (row & 7u))) << 2) + (kp & 3u);
}

// epilogue of 4 accumulator elements: w=e^{2d-2}; E+=w; W+=d*w; rezero
__device__ __forceinline__ void epi4(float* acc, int f0, float* E, float* W) {
    #pragma unroll
    for (int u = 0; u < 4; u++) {
        int f = f0 + u;
        float d = acc[f]; acc[f] = 0.f;
        float e2 = fmaf(d, 2.885390082f, -2.885390082f);   // (2d-2)*log2(e)
        float w; asm("ex2.approx.f32 %0, %1;" : "=f"(w) : "f"(e2));
        int ri = ((f >> 4) << 1) + ((f & 3) >> 1);
        E[ri] += w; W[ri] = fmaf(d, w, W[ri]);
    }
}

// MMA over one 32-col half (PBASE = 0 or 2), interleaving the epilogue of the OTHER half
template <int PBASE, bool DOEPI>
__device__ __forceinline__ void half_mma(uint32_t baseA0, uint32_t baseA1, uint32_t Brow,
                                         uint32_t hiA, uint32_t swz, uint32_t kbB,
                                         float* acc, float* oacc, float* E, float* W) {
    #pragma unroll
    for (int ks = 0; ks < 8; ks++) {
        uint32_t a0[4], a1[4];
        uint32_t offA = (((2u * (uint32_t)ks + hiA) ^ swz) << 4);
        ldsm_x4(a0, baseA0 + offA);
        ldsm_x4(a1, baseA1 + offA);
        uint32_t offB = (((2u * (uint32_t)ks + kbB) ^ swz) << 4);
        #pragma unroll
        for (int pp = 0; pp < 2; pp++) {
            uint32_t bb[4];
            ldsm_x4(bb, Brow + (uint32_t)((PBASE + pp) * 4096) + offB);
            mma_bf16(&acc[(2 * pp) * 4],          a0, bb);
            mma_bf16(&acc[(2 * pp + 1) * 4],      a0, bb + 2);
            mma_bf16(&acc[16 + (2 * pp) * 4],     a1, bb);
            mma_bf16(&acc[16 + (2 * pp + 1) * 4], a1, bb + 2);
        }
        if (DOEPI) epi4(oacc, ks * 4, E, W);
    }
}

// ---------------- merged pre-kernel ----------------
// blocks 0..511: conv_qu | 512..527: conv_q | 528..783: loss1 | 784: zero E/W
__global__ void pre_kernel(const float* __restrict__ q, const float* __restrict__ k,
                           const float* __restrict__ queue) {
    extern __shared__ float sf[];   // 128 x 65 floats (33280 B)
    const int bid = blockIdx.x, tid = threadIdx.x;
    if (bid < 512) {
        // queue [D,K] -> transposed ([n][k]) bf16 swizzled tile image, two 64-col halves
        const int t = bid;
        uint32_t* dst = g_qu + (size_t)t * TILE_U32;
        #pragma unroll
        for (int half = 0; half < 2; half++) {
            #pragma unroll 4
            for (int it = 0; it < 32; it++) {          // 128 rows x 64 cols stage
                int idx = it * 256 + tid;
                int d = idx >> 6, j = idx & 63;
                sf[d * 65 + j] = queue[(size_t)d * KK + t * 128 + half * 64 + j];
            }
            __syncthreads();
            #pragma unroll 4
            for (int it = 0; it < 16; it++) {          // 64 n x 64 kp
                int idx = it * 256 + tid;
                int nl = idx >> 6, kp = idx & 63;
                __nv_bfloat162 b = __floats2bfloat162_rn(sf[(2 * kp) * 65 + nl],
                                                         sf[(2 * kp + 1) * 65 + nl]);
                dst[tidx(half * 64 + nl, kp)] = *(uint32_t*)&b;
            }
            __syncthreads();
        }
    } else if (bid < 528) {
        // q -> bf16 swizzled tile image (tile = v*8+rb)
        const int t = bid - 512;
        const float* src = q + (size_t)t * 128 * DD;
        uint32_t* dst = g_qt + (size_t)t * TILE_U32;
        #pragma unroll 4
        for (int it = 0; it < 32; it++) {
            int idx = it * 256 + tid;
            int row = idx >> 6, kp = idx & 63;
            float2 v = *(const float2*)(src + row * DD + 2 * kp);
            __nv_bfloat162 b = __floats2bfloat162_rn(v.x, v.y);
            dst[tidx(row, kp)] = *(uint32_t*)&b;
        }
    } else if (bid < 784) {
        // loss1 partial: 8 warps, warp per row pair; lane holds one float4
        const int wid = tid >> 5, lane = tid & 31;
        const int w = (bid - 528) * 8 + wid;
        const int x = w >> 10, i = w & (NN - 1);
        float4 a = ((const float4*)(q + ((size_t)x * NN + i) * DD))[lane];
        float4 b = ((const float4*)(k + ((size_t)(1 - x) * NN + i) * DD))[lane];
        float dx = a.x - b.x, dy = a.y - b.y, dz = a.z - b.z, dw = a.w - b.w;
        float s = fmaf(dx, dx, fmaf(dy, dy, fmaf(dz, dz, dw * dw)));
        #pragma unroll
        for (int m = 16; m >= 1; m >>= 1) s += __shfl_xor_sync(0xffffffffu, s, m);
        if (lane == 0) sf[wid] = s;
        __syncthreads();
        if (tid == 0) {
            float acc = 0.f;
            #pragma unroll
            for (int j = 0; j < 8; j++) acc += sf[j];
            g_l1part[bid - 528] = acc;
        }
    } else {
        for (int i = tid; i < NV * NN; i += 256) {
            if (i < NN) { g_EQ[i] = 0.f; g_WQ[i] = 0.f; }
            g_EI[i] = 0.f; g_WI[i] = 0.f;
        }
    }
}

// ---------------- bf16 mma.sync GEMM, ping-pong halves, fused epilogue ----------------
// bid < 512: queue part: rows = q[0] block (bid>>6), B tiles = j-group (bid&63)*8
// bid >= 512: intra part: view x, row block rb; B tiles = all 8 tiles of q[x]
__global__ __launch_bounds__(256, 2) void gemm_ws() {
    extern __shared__ __align__(128) char smg[];
    const uint32_t sb = smem_u32(smg);
    const uint32_t o_A = sb, o_B0 = sb + 32768, o_B1 = sb + 65536;
    const int tid = threadIdx.x, lane = tid & 31, wid = tid >> 5;
    const int wm = wid >> 1, wn = wid & 1;        // 4x2 warps, warp tile 32x64
    const int bid = blockIdx.x;

    const uint32_t *Asrc, *Bsrc;
    float *Eout, *Wout;
    int rowbase;
    if (bid < 512) {
        int rb = bid >> 6, jg = bid & 63;
        Asrc = g_qt + (size_t)rb * TILE_U32;                  // view 0 rows
        Bsrc = g_qu + (size_t)(jg * 8) * TILE_U32;
        Eout = g_EQ; Wout = g_WQ; rowbase = rb * 128;
    } else {
        int id = bid - 512, x = id >> 3, rb = id & 7;
        Asrc = g_qt + (size_t)(x * 8 + rb) * TILE_U32;
        Bsrc = g_qt + (size_t)(x * 8) * TILE_U32;
        Eout = g_EI + x * NN; Wout = g_WI + x * NN; rowbase = rb * 128;
    }

    // prologue: A + B0 (contiguous 32KB copies), one commit group
    #pragma unroll
    for (int c = 0; c < 8; c++) cp16(o_A + (c * 256 + tid) * 16, Asrc + (c * 256 + tid) * 4);
    #pragma unroll
    for (int c = 0; c < 8; c++) cp16(o_B0 + (c * 256 + tid) * 16, Bsrc + (c * 256 + tid) * 4);
    asm volatile("cp.async.commit_group;");

    // per-lane ldmatrix address components
    const uint32_t swz = (uint32_t)(lane & 7);
    const uint32_t hiA = (uint32_t)(lane >> 4);
    const uint32_t baseA0 = o_A + (uint32_t)(wm * 32 + (lane & 15)) * 256u;
    const uint32_t baseA1 = baseA0 + 4096u;      // +16 rows
    const uint32_t nrowb = (uint32_t)(wn * 64 + ((lane >> 4) & 1) * 8 + (lane & 7));
    const uint32_t kbB = (uint32_t)((lane >> 3) & 1);

    float accA[32], accB[32];
    #pragma unroll
    for (int i = 0; i < 32; i++) { accA[i] = 0.f; accB[i] = 0.f; }
    float E[4] = {0.f, 0.f, 0.f, 0.f}, W[4] = {0.f, 0.f, 0.f, 0.f};

    for (int t = 0; t < 8; t++) {
        const int buf = t & 1;
        if (t < 7) {          // prefetch next B into the other buffer
            uint32_t dstB = buf ? o_B0 : o_B1;
            const uint32_t* s = Bsrc + (size_t)(t + 1) * TILE_U32;
            #pragma unroll
            for (int c = 0; c < 8; c++) cp16(dstB + (c * 256 + tid) * 16, s + (c * 256 + tid) * 4);
            asm volatile("cp.async.commit_group;");
            asm volatile("cp.async.wait_group 1;");
        } else {
            asm volatile("cp.async.wait_group 0;");
        }
        __syncthreads();      // current B visible to all warps

        const uint32_t Brow = (buf ? o_B1 : o_B0) + nrowb * 256u;
        // phase0: MMA half0 -> accA, overlapped with epilogue of accB (prev tile)
        if (t == 0) half_mma<0, false>(baseA0, baseA1, Brow, hiA, swz, kbB, accA, accB, E, W);
        else        half_mma<0, true >(baseA0, baseA1, Brow, hiA, swz, kbB, accA, accB, E, W);
        // phase1: MMA half1 -> accB, overlapped with epilogue of accA (this tile)
        half_mma<2, true>(baseA0, baseA1, Brow, hiA, swz, kbB, accB, accA, E, W);
        __syncthreads();      // all warps done reading B[t] before overwrite
    }
    #pragma unroll
    for (int f = 0; f < 32; f += 4) epi4(accB, f, E, W);   // drain last half

    // reduce over the 4 lanes sharing each row, then atomics
    #pragma unroll
    for (int m = 1; m < 4; m <<= 1)
        #pragma unroll
        for (int ri = 0; ri < 4; ri++) {
            E[ri] += __shfl_xor_sync(0xffffffffu, E[ri], m);
            W[ri] += __shfl_xor_sync(0xffffffffu, W[ri], m);
        }
    if ((lane & 3) == 0) {
        int g = lane >> 2;
        #pragma unroll
        for (int mt = 0; mt < 2; mt++)
            #pragma unroll
            for (int h = 0; h < 2; h++) {
                int row = rowbase + wm * 32 + mt * 16 + 8 * h + g;
                atomicAdd(&Eout[row], E[mt * 2 + h]);
                atomicAdd(&Wout[row], W[mt * 2 + h]);
            }
    }
}

__global__ void finalize_kernel(float* __restrict__ out) {
    int i = threadIdx.x;   // 1024 threads
    float v = 0.f;
    #pragma unroll
    for (int x = 0; x < NV; x++) {
        float S  = g_EQ[i] + g_EI[x * NN + i];   // sum e^{-s} incl. diagonal (=1)
        float Wt = g_WQ[i] + g_WI[x * NN + i];   // sum d*e^{-s}
        float T = 2.f * (S - Wt);                // sum s*e^{-s} (diag adds 0)
        float E = S - 1.f;                       // drop diagonal
        v -= T / E;
    }
    float l1 = (i < 256) ? g_l1part[i] : 0.f;
    __shared__ float r2[32], r1[32];
    #pragma unroll
    for (int m = 16; m >= 1; m >>= 1) {
        v  += __shfl_xor_sync(0xffffffffu, v, m);
        l1 += __shfl_xor_sync(0xffffffffu, l1, m);
    }
    if ((i & 31) == 0) { r2[i >> 5] = v; r1[i >> 5] = l1; }
    __syncthreads();
    if (i < 32) {
        float w = r2[i], u = r1[i];
        #pragma unroll
        for (int m = 16; m >= 1; m >>= 1) {
            w += __shfl_xor_sync(0xffffffffu, w, m);
            u += __shfl_xor_sync(0xffffffffu, u, m);
        }
        if (i == 0) {
            out[0] = u * (1.0f / (NV * NN));
            out[1] = w * (1.0f / (NV * NN));
        }
    }
}

// ---------------- launcher ----------------
extern "C" void kernel_launch(void* const* d_in, const int* in_sizes, int n_in,
                              void* d_out, int out_size) {
    const float* q     = (const float*)d_in[0];
    const float* k     = (const float*)d_in[1];
    const float* queue = (const float*)d_in[2];
    float* out = (float*)d_out;

    const int smem_gemm = 3 * 32768;              // A + B double buffer = 96KB
    const int smem_pre  = 128 * 65 * 4;           // 33280
    cudaFuncSetAttribute(gemm_ws,    cudaFuncAttributeMaxDynamicSharedMemorySize, smem_gemm);
    cudaFuncSetAttribute(pre_kernel, cudaFuncAttributeMaxDynamicSharedMemorySize, smem_pre);

    pre_kernel<<<785, 256, smem_pre>>>(q, k, queue);
    gemm_ws<<<512 + 16, 256, smem_gemm>>>();
    finalize_kernel<<<1, 1024>>>(out);
}